// round 3
// baseline (speedup 1.0000x reference)
#include <cuda_runtime.h>
#include <cstdint>

#define GRID_DIM   128
#define U_PIX      8192
#define N_TRK      3000
#define M_NEIGH    16
#define T_SIG      400
#define ADC_SAMPLE 50
#define NBINS      200          // T_TOTAL / ADC_SAMPLE
#define GAIN       0.25f
#define PEDESTAL   74.0f
#define ADC_MAX    255.0f

// Scratch (allocation-free rule: __device__ globals).
// g_acc relies on CUDA zero-initialization at module load for the FIRST call;
// k_final re-zeroes every row it reads, so each subsequent call (and every
// graph replay) also starts from zeros. Deterministic across calls.
__device__ int   g_lut[GRID_DIM * GRID_DIM];     // (y,x) -> unique pixel id, -1 = none
__device__ float g_acc[U_PIX * NBINS];           // per-pixel per-50-sample-bin sums

// ---------------------------------------------------------------------------
// Kernel 1: invalidate LUT (tiny: 64 KB)
// ---------------------------------------------------------------------------
__global__ void k_init() {
    int tid = blockIdx.x * blockDim.x + threadIdx.x;
    if (tid < GRID_DIM * GRID_DIM) g_lut[tid] = -1;
}

// ---------------------------------------------------------------------------
// Kernel 2: scatter unique_pix into the LUT (coords unique by construction)
// ---------------------------------------------------------------------------
__global__ void k_lut(const int2* __restrict__ unique_pix) {
    int u = blockIdx.x * blockDim.x + threadIdx.x;
    if (u >= U_PIX) return;
    int2 c = unique_pix[u];
    g_lut[c.x * GRID_DIM + c.y] = u;
}

// ---------------------------------------------------------------------------
// Kernel 3: one warp per (track, neighbor) pair.
// Coalesced float4 loads (100 per signal), per-lane chunk spans <=2 bins ->
// <=2 shared atomicAdds into a per-warp 16-entry bin array, then lanes 0..8
// flush once to the L2-resident global accumulator.
// ---------------------------------------------------------------------------
__global__ void k_accum(const int2*  __restrict__ neigh,
                        const float* __restrict__ sig,
                        const int*   __restrict__ starts) {
    __shared__ float sbin[8][16];                 // 8 warps/block, bins 0..8 used

    int gwarp = (blockIdx.x * blockDim.x + threadIdx.x) >> 5;
    int lane  = threadIdx.x & 31;
    int wib   = (threadIdx.x >> 5);               // warp in block
    if (gwarp >= N_TRK * M_NEIGH) return;

    int2 c = neigh[gwarp];
    if (c.x < 0) return;                          // dead channel -> discard

    int pid = g_lut[c.x * GRID_DIM + c.y];
    if (pid < 0) return;

    int n     = gwarp >> 4;                       // M_NEIGH = 16
    int start = starts[n];
    int b0    = start / ADC_SAMPLE;               // 0..191
    int rel0  = start - b0 * ADC_SAMPLE;          // 0..49

    float* sb = sbin[wib];
    if (lane < 16) sb[lane] = 0.0f;
    __syncwarp();

    const float4* s4 = reinterpret_cast<const float4*>(sig + (size_t)gwarp * T_SIG);

    #pragma unroll
    for (int j = 0; j < 4; ++j) {
        int cidx = j * 32 + lane;                 // float4 chunk index, 0..99
        if (cidx < 100) {
            float4 f   = s4[cidx];
            int    r0  = rel0 + 4 * cidx;         // rel pos of f.x, 0..445
            int    li0 = r0 / 50;                 // local bin of first elem
            int    li3 = (r0 + 3) / 50;           // local bin of last elem
            float  tot = (f.x + f.y) + (f.z + f.w);
            if (li0 == li3) {
                atomicAdd(&sb[li0], tot);
            } else {
                int   nhi = r0 + 4 - li3 * 50;    // elems in upper bin: 1..3
                float hi  = f.w;
                if (nhi >= 2) hi += f.z;
                if (nhi >= 3) hi += f.y;
                atomicAdd(&sb[li0], tot - hi);
                atomicAdd(&sb[li3], hi);
            }
        }
    }
    __syncwarp();

    // local bin max = (rel0 + 399)/50 <= 8; b0 + 8 <= 199 always
    if (lane < 9)
        atomicAdd(&g_acc[(size_t)pid * NBINS + b0 + lane], sb[lane]);
}

// ---------------------------------------------------------------------------
// Kernel 4: one warp per pixel row. Both chunk loads issued up front; the two
// warp scans run interleaved (ILP) in one 5-stage shuffle chain; chunk-1 base
// gets chunk-0's total afterward. Fused affine + clip; re-zeroes g_acc row.
// ---------------------------------------------------------------------------
__global__ void k_final(float* __restrict__ out) {
    int gwarp = (blockIdx.x * blockDim.x + threadIdx.x) >> 5;
    int lane  = threadIdx.x & 31;
    if (gwarp >= U_PIX) return;

    float4* row4 = reinterpret_cast<float4*>(g_acc + (size_t)gwarp * NBINS);
    float4* out4 = reinterpret_cast<float4*>(out + (size_t)gwarp * NBINS);

    const float4 z4 = make_float4(0.f, 0.f, 0.f, 0.f);
    bool act1 = (lane < NBINS / 4 - 32);          // lanes 0..17

    float4 x0 = row4[lane];                       // elements 0..127
    float4 x1 = act1 ? row4[32 + lane] : z4;      // elements 128..199

    // inclusive scan within each vector
    x0.y += x0.x;  x0.z += x0.y;  x0.w += x0.z;
    x1.y += x1.x;  x1.z += x1.y;  x1.w += x1.z;
    float s0 = x0.w, s1 = x1.w;

    // two interleaved warp inclusive scans (one shared 5-stage latency chain)
    float i0 = s0, i1 = s1;
    #pragma unroll
    for (int o = 1; o < 32; o <<= 1) {
        float u0 = __shfl_up_sync(0xffffffffu, i0, o);
        float u1 = __shfl_up_sync(0xffffffffu, i1, o);
        if (lane >= o) { i0 += u0; i1 += u1; }
    }
    float tot0  = __shfl_sync(0xffffffffu, i0, 31);
    float base0 = i0 - s0;                        // exclusive prefix chunk 0
    float base1 = tot0 + (i1 - s1);               // exclusive prefix chunk 1

    float4 r;
    r.x = fminf(fmaxf((x0.x + base0) * GAIN + PEDESTAL, 0.0f), ADC_MAX);
    r.y = fminf(fmaxf((x0.y + base0) * GAIN + PEDESTAL, 0.0f), ADC_MAX);
    r.z = fminf(fmaxf((x0.z + base0) * GAIN + PEDESTAL, 0.0f), ADC_MAX);
    r.w = fminf(fmaxf((x0.w + base0) * GAIN + PEDESTAL, 0.0f), ADC_MAX);
    out4[lane] = r;
    row4[lane] = z4;                              // re-zero accumulator row
    if (act1) {
        r.x = fminf(fmaxf((x1.x + base1) * GAIN + PEDESTAL, 0.0f), ADC_MAX);
        r.y = fminf(fmaxf((x1.y + base1) * GAIN + PEDESTAL, 0.0f), ADC_MAX);
        r.z = fminf(fmaxf((x1.z + base1) * GAIN + PEDESTAL, 0.0f), ADC_MAX);
        r.w = fminf(fmaxf((x1.w + base1) * GAIN + PEDESTAL, 0.0f), ADC_MAX);
        out4[32 + lane] = r;
        row4[32 + lane] = z4;                     // re-zero accumulator row
    }
}

// ---------------------------------------------------------------------------
// Launch
// ---------------------------------------------------------------------------
extern "C" void kernel_launch(void* const* d_in, const int* in_sizes, int n_in,
                              void* d_out, int out_size) {
    const int2*  neigh  = (const int2*) d_in[0];   // (3000, 16, 2) int32
    const int2*  upix   = (const int2*) d_in[1];   // (8192, 2) int32
    const float* sig    = (const float*)d_in[2];   // (3000, 16, 400) float32
    const int*   starts = (const int*)  d_in[3];   // (3000,) int32
    float*       out    = (float*)      d_out;     // (8192, 200) float32

    (void)in_sizes; (void)n_in; (void)out_size;

    k_init<<<(GRID_DIM * GRID_DIM + 255) / 256, 256>>>();
    k_lut<<<(U_PIX + 255) / 256, 256>>>(upix);

    {
        int total_warps = N_TRK * M_NEIGH;         // 48000
        int threads = 256;
        int blocks  = (total_warps * 32 + threads - 1) / threads;
        k_accum<<<blocks, threads>>>(neigh, sig, starts);
    }
    {
        int threads = 256;
        int blocks  = (U_PIX * 32 + threads - 1) / threads;   // 1024
        k_final<<<blocks, threads>>>(out);
    }
}